// round 5
// baseline (speedup 1.0000x reference)
#include <cuda_runtime.h>
#include <cstdint>
#include <math.h>

// Kendall's tau loss via discordant-pair count (no ties in random normals):
//   loss = 4*D / (n(n-1)),  D = #{i<j : sign(p_i-p_j) != sign(t_i-t_j)}
// Per pair: FADD2 (packed f32x2 diff) + LOP3 (xor) + 1 accumulate.
// R5: TILE=128 / NTH=64 / 2 rows -> 2080 blocks (~28 warps/SM, occ ~44%);
// chain 0 accumulates on alu pipe (LEA.HI), chain 1 on fma pipe via
// mad.hi.u32 with a non-foldable multiplier (blockDim.x>>5 == 2).

#define TILE 128
#define NTH 64

__device__ unsigned long long g_cnt = 0;
__device__ unsigned int g_done = 0;

__device__ __forceinline__ unsigned long long pack2(float lo, float hi) {
    unsigned long long r;
    asm("mov.b64 %0, {%1, %2};" : "=l"(r) : "f"(lo), "f"(hi));
    return r;
}

__device__ __forceinline__ unsigned int xor_word(unsigned long long a,
                                                 unsigned long long nb) {
    unsigned long long s;
    asm("add.rn.f32x2 %0, %1, %2;" : "=l"(s) : "l"(a), "l"(nb));
    unsigned int lo, hi;
    asm("mov.b64 {%0, %1}, %2;" : "=r"(lo), "=r"(hi) : "l"(s));
    return lo ^ hi;
}

// alu-pipe accumulate: LOP3 + LEA.HI (c += bit31)
__device__ __forceinline__ void acc_alu(unsigned int& c, unsigned long long a,
                                        unsigned long long nb) {
    c += xor_word(a, nb) >> 31;
}
// fma-pipe accumulate: LOP3 + IMAD.HI.U32. 'two' is runtime-opaque (==2),
// so ptxas cannot strength-reduce the mad.hi back to a shift.
__device__ __forceinline__ void acc_fma(unsigned int& c, unsigned long long a,
                                        unsigned long long nb,
                                        unsigned int two) {
    unsigned int x = xor_word(a, nb);
    asm("mad.hi.u32 %0, %1, %2, %0;" : "+r"(c) : "r"(x), "r"(two));
}

__global__ __launch_bounds__(NTH) void kt_kernel(
    const float* __restrict__ p, const float* __restrict__ t,
    float* __restrict__ out, int n)
{
    const int ntiles = (n + TILE - 1) / TILE;
    const unsigned int two = blockDim.x >> 5;  // == 2, opaque to ptxas

    // Closed-form decode: linear b -> (bi, bj), bj >= bi, row-major rows.
    const int b = blockIdx.x;
    int bi = (int)((2.0 * ntiles + 1.0 -
                    sqrt((2.0 * ntiles + 1.0) * (2.0 * ntiles + 1.0) -
                         8.0 * (double)b)) * 0.5);
    // fixup for fp rounding
    while (bi > 0 && b < bi * ntiles - (bi * (bi - 1)) / 2) --bi;
    while (b >= (bi + 1) * ntiles - ((bi + 1) * bi) / 2) ++bi;
    const int bj = bi + (b - (bi * ntiles - (bi * (bi - 1)) / 2));

    __shared__ __align__(16) float2 snb[TILE];  // (-p_j, -t_j)

    const int tid = threadIdx.x;
    const int jb = bj * TILE;
    const int jlim = min(TILE, n - jb);

    #pragma unroll
    for (int k = tid; k < TILE; k += NTH)
        if (k < jlim) snb[k] = make_float2(-p[jb + k], -t[jb + k]);
    __syncthreads();

    const int ib = bi * TILE;
    unsigned int c0 = 0, c1 = 0;

    const bool full = (jlim == TILE) && (ib + TILE <= n);

    if (full && bi != bj) {
        // Full off-diagonal tile: all (i, j) valid. 2 rows/thread.
        const unsigned long long a0 = pack2(p[ib + tid      ], t[ib + tid      ]);
        const unsigned long long a1 = pack2(p[ib + tid + NTH], t[ib + tid + NTH]);
        const ulonglong2* B2 = reinterpret_cast<const ulonglong2*>(snb);
        #pragma unroll 8
        for (int k2 = 0; k2 < TILE / 2; ++k2) {
            const ulonglong2 bb = B2[k2];      // two consecutive j's, LDS.128
            acc_alu(c0, a0, bb.x);
            acc_fma(c1, a1, bb.x, two);
            acc_alu(c0, a0, bb.y);
            acc_fma(c1, a1, bb.y, two);
        }
    } else if (full) {
        // Diagonal tile: local j > local i.
        const unsigned long long* B =
            reinterpret_cast<const unsigned long long*>(snb);
        const unsigned long long a0 = pack2(p[ib + tid      ], t[ib + tid      ]);
        const unsigned long long a1 = pack2(p[ib + tid + NTH], t[ib + tid + NTH]);
        #pragma unroll 4
        for (int k = tid + 1; k < TILE; ++k) acc_alu(c0, a0, B[k]);
        #pragma unroll 4
        for (int k = tid + NTH + 1; k < TILE; ++k) acc_fma(c1, a1, B[k], two);
    } else {
        // Partial tile (not hit for n=8192; kept for generality).
        const unsigned long long* B =
            reinterpret_cast<const unsigned long long*>(snb);
        #pragma unroll
        for (int r = 0; r < 2; ++r) {
            const int i = ib + tid + r * NTH;
            if (i < n) {
                const unsigned long long a = pack2(p[i], t[i]);
                for (int k = 0; k < jlim; ++k)
                    if (jb + k > i) acc_alu(c0, a, B[k]);
            }
        }
    }

    unsigned int cnt = c0 + c1;

    #pragma unroll
    for (int off = 16; off > 0; off >>= 1)
        cnt += __shfl_down_sync(0xFFFFFFFFu, cnt, off);

    __shared__ unsigned int wsum[NTH / 32];
    if ((tid & 31) == 0) wsum[tid >> 5] = cnt;
    __syncthreads();

    if (tid == 0) {
        unsigned int total = 0;
        #pragma unroll
        for (int w = 0; w < NTH / 32; ++w) total += wsum[w];

        atomicAdd(&g_cnt, (unsigned long long)total);
        __threadfence();
        const unsigned int d = atomicAdd(&g_done, 1u);
        if (d == gridDim.x - 1) {
            const unsigned long long D = atomicAdd(&g_cnt, 0ULL);
            const double nn = (double)n;
            out[0] = (float)(4.0 * (double)D / (nn * (nn - 1.0)));
            g_cnt = 0ULL;   // reset for next graph replay
            g_done = 0u;
        }
    }
}

extern "C" void kernel_launch(void* const* d_in, const int* in_sizes, int n_in,
                              void* d_out, int out_size)
{
    const float* predictions = (const float*)d_in[0];
    const float* true_labels = (const float*)d_in[1];
    float* out = (float*)d_out;
    const int n = in_sizes[0];

    const int ntiles = (n + TILE - 1) / TILE;
    const int nblocks = ntiles * (ntiles + 1) / 2;

    kt_kernel<<<nblocks, NTH>>>(predictions, true_labels, out, n);
}

// round 6
// speedup vs baseline: 1.2618x; 1.2618x over previous
#include <cuda_runtime.h>
#include <cstdint>

// Kendall's tau loss via discordant-pair count (no ties in random normals):
//   loss = 4*D / (n(n-1)),  D = #{i<j : sign(p_i-p_j) != sign(t_i-t_j)}
// Per pair: FADD2 (packed f32x2 diff, fma pipe) + LOP3 (alu) + accumulate.
// R6: R3's best shape (TILE=256, NTH=128, 528 blocks) with
//  - pipe-balanced accumulate (row0: LEA.HI/alu, row1: IMAD.HI/fma)
//  - register double-buffered LDS.128 stream (hide 29cyc smem latency)
//  - REDUX.SUM warp reduction instead of 5-deep SHFL chain.

#define TILE 256
#define NTH 128

__device__ unsigned long long g_cnt = 0;
__device__ unsigned int g_done = 0;

__device__ __forceinline__ unsigned long long pack2(float lo, float hi) {
    unsigned long long r;
    asm("mov.b64 %0, {%1, %2};" : "=l"(r) : "f"(lo), "f"(hi));
    return r;
}

__device__ __forceinline__ unsigned int xor_word(unsigned long long a,
                                                 unsigned long long nb) {
    unsigned long long s;
    asm("add.rn.f32x2 %0, %1, %2;" : "=l"(s) : "l"(a), "l"(nb));
    unsigned int lo, hi;
    asm("mov.b64 {%0, %1}, %2;" : "=r"(lo), "=r"(hi) : "l"(s));
    return lo ^ hi;
}

// alu-pipe accumulate: LOP3 + LEA.HI (c += bit31)
__device__ __forceinline__ void acc_alu(unsigned int& c, unsigned long long a,
                                        unsigned long long nb) {
    c += xor_word(a, nb) >> 31;
}
// fma-pipe accumulate: LOP3 + IMAD.HI.U32 with runtime-opaque multiplier (==2)
__device__ __forceinline__ void acc_fma(unsigned int& c, unsigned long long a,
                                        unsigned long long nb,
                                        unsigned int two) {
    unsigned int x = xor_word(a, nb);
    asm("mad.hi.u32 %0, %1, %2, %0;" : "+r"(c) : "r"(x), "r"(two));
}

__global__ __launch_bounds__(NTH) void kt_kernel(
    const float* __restrict__ p, const float* __restrict__ t,
    float* __restrict__ out, int n)
{
    const int ntiles = (n + TILE - 1) / TILE;
    const unsigned int two = (unsigned int)blockDim.x >> 6;  // ==2, opaque

    // Linear block id -> upper-triangular (bi, bj), bj >= bi.
    int b = blockIdx.x;
    int bi = 0;
    while (b >= ntiles - bi) { b -= ntiles - bi; ++bi; }
    const int bj = bi + b;

    __shared__ __align__(16) float2 snb[TILE];  // (-p_j, -t_j)

    const int tid = threadIdx.x;
    const int jb = bj * TILE;
    const int jlim = min(TILE, n - jb);

    #pragma unroll
    for (int k = tid; k < TILE; k += NTH)
        if (k < jlim) snb[k] = make_float2(-p[jb + k], -t[jb + k]);
    __syncthreads();

    const int ib = bi * TILE;
    unsigned int c0 = 0, c1 = 0;

    const bool full = (jlim == TILE) && (ib + TILE <= n);

    if (full && bi != bj) {
        // Full off-diagonal tile: all (i, j) valid. 2 rows/thread.
        const unsigned long long a0 = pack2(p[ib + tid      ], t[ib + tid      ]);
        const unsigned long long a1 = pack2(p[ib + tid + NTH], t[ib + tid + NTH]);

        const ulonglong2* B2 = reinterpret_cast<const ulonglong2*>(snb);
        ulonglong2 cur = B2[0];
        #pragma unroll 16
        for (int k2 = 0; k2 < TILE / 2 - 1; ++k2) {
            const ulonglong2 nxt = B2[k2 + 1];   // prefetch next LDS.128
            acc_alu(c0, a0, cur.x);
            acc_fma(c1, a1, cur.x, two);
            acc_alu(c0, a0, cur.y);
            acc_fma(c1, a1, cur.y, two);
            cur = nxt;
        }
        acc_alu(c0, a0, cur.x);
        acc_fma(c1, a1, cur.x, two);
        acc_alu(c0, a0, cur.y);
        acc_fma(c1, a1, cur.y, two);
    } else if (full) {
        // Diagonal tile: local j > local i.
        const unsigned long long* B =
            reinterpret_cast<const unsigned long long*>(snb);
        const unsigned long long a0 = pack2(p[ib + tid      ], t[ib + tid      ]);
        const unsigned long long a1 = pack2(p[ib + tid + NTH], t[ib + tid + NTH]);
        #pragma unroll 8
        for (int k = tid + 1; k < TILE; ++k) acc_alu(c0, a0, B[k]);
        #pragma unroll 8
        for (int k = tid + NTH + 1; k < TILE; ++k) acc_fma(c1, a1, B[k], two);
    } else {
        // Partial tile (not hit for n=8192; kept for generality).
        const unsigned long long* B =
            reinterpret_cast<const unsigned long long*>(snb);
        #pragma unroll
        for (int r = 0; r < 2; ++r) {
            const int i = ib + tid + r * NTH;
            if (i < n) {
                const unsigned long long a = pack2(p[i], t[i]);
                for (int k = 0; k < jlim; ++k)
                    if (jb + k > i) acc_alu(c0, a, B[k]);
            }
        }
    }

    // Warp reduction: single REDUX.SUM instead of 5 dependent SHFLs.
    unsigned int cnt = __reduce_add_sync(0xFFFFFFFFu, c0 + c1);

    __shared__ unsigned int wsum[NTH / 32];
    if ((tid & 31) == 0) wsum[tid >> 5] = cnt;
    __syncthreads();

    if (tid == 0) {
        unsigned int total = 0;
        #pragma unroll
        for (int w = 0; w < NTH / 32; ++w) total += wsum[w];

        atomicAdd(&g_cnt, (unsigned long long)total);
        __threadfence();
        const unsigned int d = atomicAdd(&g_done, 1u);
        if (d == gridDim.x - 1) {
            const unsigned long long D = atomicAdd(&g_cnt, 0ULL);
            const double nn = (double)n;
            out[0] = (float)(4.0 * (double)D / (nn * (nn - 1.0)));
            g_cnt = 0ULL;   // reset for next graph replay
            g_done = 0u;
        }
    }
}

extern "C" void kernel_launch(void* const* d_in, const int* in_sizes, int n_in,
                              void* d_out, int out_size)
{
    const float* predictions = (const float*)d_in[0];
    const float* true_labels = (const float*)d_in[1];
    float* out = (float*)d_out;
    const int n = in_sizes[0];

    const int ntiles = (n + TILE - 1) / TILE;
    const int nblocks = ntiles * (ntiles + 1) / 2;

    kt_kernel<<<nblocks, NTH>>>(predictions, true_labels, out, n);
}